// round 10
// baseline (speedup 1.0000x reference)
#include <cuda_runtime.h>
#include <cstdint>

#define Bz    4
#define Cc    64
#define Hh    64
#define Ww    64
#define HW    4096
#define CHW   (Cc*HW)
#define PATCH 9
#define CHUNK 16
#define NCH   (Cc/CHUNK)            // 4
#define XW    32                    // x extent per CTA
#define SROW  40                    // 4 | 32 | 4 (floats)
#define NROWS 9                     // f2 rows per tile
#define F2BUF (CHUNK*NROWS*SROW)    // 5760 floats
#define F1BUF (CHUNK*XW)            // 512 floats
#define SMEM_FLOATS (2*(F2BUF+F1BUF))  // 12544
#define SMEM_BYTES  (SMEM_FLOATS*4)    // 50176
#define NTHR  288                   // 9 warps (warp = dy)
#define NARRIVE 160                 // 144 f2-row + 16 f1 copiers
#define CSTRIDE 40                  // combine scratch stride (floats)

typedef unsigned long long u64;

// scratch
__device__ float g_inv1[Bz][HW];
__device__ float g_inv2[Bz][HW];
__device__ float g_f2n[Bz][Cc][72][72];   // f2*inv2, zero-padded halos
__device__ float g_f1n[Bz][Cc][Hh][Ww];   // f1*inv1

__device__ __forceinline__ uint32_t smem_u32(const void* p) {
    uint32_t a;
    asm("{ .reg .u64 t; cvta.to.shared.u64 t, %1; cvt.u32.u64 %0, t; }" : "=r"(a) : "l"(p));
    return a;
}
__device__ __forceinline__ void bulk_g2s(uint32_t dst, const float* src, uint32_t bytes,
                                         uint32_t mbar) {
    asm volatile("cp.async.bulk.shared::cta.global.mbarrier::complete_tx::bytes "
                 "[%0], [%1], %2, [%3];"
                 :: "r"(dst), "l"(src), "r"(bytes), "r"(mbar) : "memory");
}
__device__ __forceinline__ void mbar_init(uint32_t mbar, uint32_t cnt) {
    asm volatile("mbarrier.init.shared.b64 [%0], %1;" :: "r"(mbar), "r"(cnt) : "memory");
}
__device__ __forceinline__ void mbar_arrive_tx(uint32_t mbar, uint32_t tx) {
    asm volatile("mbarrier.arrive.expect_tx.shared.b64 _, [%0], %1;"
                 :: "r"(mbar), "r"(tx) : "memory");
}
__device__ __forceinline__ void mbar_wait(uint32_t mbar, uint32_t parity) {
    uint32_t done;
    asm volatile("{\n\t.reg .pred p;\n\t"
                 "mbarrier.try_wait.parity.acquire.cta.shared::cta.b64 p, [%1], %2;\n\t"
                 "selp.b32 %0, 1, 0, p;\n\t}"
                 : "=r"(done) : "r"(mbar), "r"(parity) : "memory");
    if (!done) {
        asm volatile("{\n\t.reg .pred P1;\n\t"
                     "WL_%=:\n\t"
                     "mbarrier.try_wait.parity.acquire.cta.shared::cta.b64 P1, [%0], %1, 0x989680;\n\t"
                     "@P1 bra.uni WD_%=;\n\t"
                     "bra.uni WL_%=;\n\t"
                     "WD_%=:\n\t}"
                     :: "r"(mbar), "r"(parity) : "memory");
    }
}
__device__ __forceinline__ u64 pk(float lo, float hi) {
    u64 r; asm("mov.b64 %0, {%1, %2};" : "=l"(r) : "f"(lo), "f"(hi)); return r;
}
__device__ __forceinline__ void fma2(u64& d, u64 a, u64 b) {
    asm("fma.rn.f32x2 %0, %1, %2, %0;" : "+l"(d) : "l"(a), "l"(b));
}
__device__ __forceinline__ void unpk(u64 p, float& lo, float& hi) {
    asm("mov.b64 {%0, %1}, %2;" : "=f"(lo), "=f"(hi) : "l"(p));
}

// ---------------------------------------------------------------------------
// Kernel 1: inverse L2 norms (flat maps). 32768 threads, MLP=16, shfl-reduce.
// ---------------------------------------------------------------------------
__global__ void invnorm_kernel(const float* __restrict__ f1,
                               const float* __restrict__ f2) {
    int idx  = blockIdx.x * 256 + threadIdx.x;
    int cg   = idx & 3;
    int quad = (idx >> 2) & 1023;
    int b    = (idx >> 12) & 3;
    int feat = idx >> 14;
    const float* src = (feat ? f2 : f1) + b * CHW + quad * 4 + cg * 16 * HW;

    float4 s = make_float4(0.f, 0.f, 0.f, 0.f);
#pragma unroll
    for (int i = 0; i < 16; ++i) {
        float4 v = __ldg((const float4*)(src + i * HW));
        s.x += v.x * v.x; s.y += v.y * v.y; s.z += v.z * v.z; s.w += v.w * v.w;
    }
#pragma unroll
    for (int m = 1; m <= 2; m <<= 1) {
        s.x += __shfl_xor_sync(0xffffffffu, s.x, m);
        s.y += __shfl_xor_sync(0xffffffffu, s.y, m);
        s.z += __shfl_xor_sync(0xffffffffu, s.z, m);
        s.w += __shfl_xor_sync(0xffffffffu, s.w, m);
    }
    if (cg == 0) {
        float4 r;
        r.x = rsqrtf(s.x + 1e-6f); r.y = rsqrtf(s.y + 1e-6f);
        r.z = rsqrtf(s.z + 1e-6f); r.w = rsqrtf(s.w + 1e-6f);
        if (feat == 0) *(float4*)&g_inv1[b][quad * 4] = r;
        else           *(float4*)&g_inv2[b][quad * 4] = r;
    }
}

// ---------------------------------------------------------------------------
// Kernel 2: normalize + pad into scratch.
//   f2n: 331776 quads (zero halos), f1n: 262144 quads. 2320 blocks x 256.
// ---------------------------------------------------------------------------
__global__ void normpad_kernel(const float* __restrict__ f1,
                               const float* __restrict__ f2) {
    int idx = blockIdx.x * 256 + threadIdx.x;
    if (idx < Bz * Cc * 72 * 18) {
        int xq = idx % 18;
        int t  = idx / 18;
        int r  = t % 72;  t /= 72;
        int c  = t & 63;
        int b  = t >> 6;
        int y  = r - 4;
        float4 val = make_float4(0.f, 0.f, 0.f, 0.f);
        if (y >= 0 && y < Hh && xq >= 1 && xq <= 16) {
            int x = (xq - 1) * 4;
            float4 v  = *(const float4*)(f2 + (b * Cc + c) * HW + y * Ww + x);
            float4 iv = *(const float4*)(&g_inv2[b][y * Ww + x]);
            val = make_float4(v.x * iv.x, v.y * iv.y, v.z * iv.z, v.w * iv.w);
        }
        *(float4*)&g_f2n[b][c][r][xq * 4] = val;
    } else {
        int j  = idx - Bz * Cc * 72 * 18;
        int xq = j & 15;
        int t  = j >> 4;
        int y  = t & 63;  t >>= 6;
        int c  = t & 63;
        int b  = t >> 6;
        int x  = xq * 4;
        float4 v  = *(const float4*)(f1 + (b * Cc + c) * HW + y * Ww + x);
        float4 iv = *(const float4*)(&g_inv1[b][y * Ww + x]);
        *(float4*)&g_f1n[b][c][y][x] =
            make_float4(v.x * iv.x, v.y * iv.y, v.z * iv.z, v.w * iv.w);
    }
}

// ---------------------------------------------------------------------------
// Kernel 3: correlation + relu.
//   grid = [b:4][y:64][xhalf:2] = 512 CTAs, 288 threads (9 warps = 9 dy).
//   lane = (ch:2bits, xq:3bits): 4 px, quarter of the channels, all 9 dx.
//   Operands pre-normalized: staging is unconditional bulk copies; epilogue
//   is pure relu. Channel quarters combined via smem.
// ---------------------------------------------------------------------------
__global__ __launch_bounds__(NTHR, 3)
void corr_kernel(float* __restrict__ out) {
    extern __shared__ float smem[];
    __shared__ u64 s_mbar[2];

    float* s_f2 = smem;                 // [2][CHUNK][NROWS][SROW]
    float* s_f1 = smem + 2 * F2BUF;     // [2][CHUNK][XW]
    const uint32_t s2 = smem_u32(s_f2);
    const uint32_t s1 = smem_u32(s_f1);
    const uint32_t mb0 = smem_u32(&s_mbar[0]);
    const uint32_t mb1 = smem_u32(&s_mbar[1]);

    const int b    = blockIdx.x >> 7;
    const int y    = (blockIdx.x >> 1) & 63;
    const int h    = blockIdx.x & 1;
    const int xb   = h * XW;
    const int tid  = threadIdx.x;
    const int dy   = tid >> 5;                // warp = dy
    const int lane = tid & 31;
    const int ch   = lane >> 3;               // channel quarter (0..3)
    const int xq   = lane & 7;                // x quad
    const int x0   = xq << 2;                 // local x
    const int xg   = xb + x0;

    const float* f2base = &g_f2n[b][0][0][0];
    const float* f1base = &g_f1n[b][0][0][0];

    // per-thread copier indices (stage geometry is chunk-invariant)
    const int cs = tid / NROWS;                // f2 copier: channel
    const int rs = tid - cs * NROWS;           //            row
    const int c1 = tid - CHUNK * NROWS;        // f1 copier: channel

    if (tid == 0) { mbar_init(mb0, NARRIVE); mbar_init(mb1, NARRIVE); }
    __syncthreads();

    auto stage = [&](int c0, int sel) {
        uint32_t mb = sel ? mb1 : mb0;
        if (tid < CHUNK * NROWS) {             // 144 copiers: one f2 row, 160B
            mbar_arrive_tx(mb, SROW * 4);
            bulk_g2s(s2 + (uint32_t)((sel * F2BUF + (cs * NROWS + rs) * SROW) * 4),
                     f2base + (c0 + cs) * (72 * 72) + (y + rs) * 72 + xb,
                     SROW * 4, mb);
        } else if (tid < NARRIVE) {            // 16 copiers: one f1 row, 128B
            mbar_arrive_tx(mb, XW * 4);
            bulk_g2s(s1 + (uint32_t)((sel * F1BUF + c1 * XW) * 4),
                     f1base + (c0 + c1) * HW + y * Ww + xb, XW * 4, mb);
        }
    };

    // acc: even dx e=d/2 as (px0,px1),(px2,px3); odd dx o as (px0,px1),(px2,px3)
    u64 accE[5][2], accO[4][2];
#pragma unroll
    for (int e = 0; e < 5; ++e) { accE[e][0] = 0ull; accE[e][1] = 0ull; }
#pragma unroll
    for (int o = 0; o < 4; ++o) { accO[o][0] = 0ull; accO[o][1] = 0ull; }

    stage(0, 0);
    stage(CHUNK, 1);

#pragma unroll 1
    for (int k = 0; k < NCH; ++k) {
        mbar_wait(k & 1 ? mb1 : mb0, (k >> 1) & 1);

        const float* sbuf = s_f2 + (k & 1) * F2BUF + dy * SROW + x0;
        const float* abuf = s_f1 + (k & 1) * F1BUF + x0;
#pragma unroll
        for (int i = 0; i < CHUNK / 4; ++i) {
            const int c = (i << 2) + ch;               // this quarter's channel
            const float* v = sbuf + c * (NROWS * SROW);
            float4 v0 = *(const float4*)(v);
            float4 v1 = *(const float4*)(v + 4);
            float4 v2 = *(const float4*)(v + 8);
            float4 af = *(const float4*)(abuf + c * XW);

            u64 w0 = pk(v0.x, v0.y), w1 = pk(v0.z, v0.w);
            u64 w2 = pk(v1.x, v1.y), w3 = pk(v1.z, v1.w);
            u64 w4 = pk(v2.x, v2.y), w5 = pk(v2.z, v2.w);
            u64 o0 = pk(v0.y, v0.z), o1 = pk(v0.w, v1.x);
            u64 o2 = pk(v1.y, v1.z), o3 = pk(v1.w, v2.x);
            u64 o4 = pk(v2.y, v2.z);
            u64 a01 = pk(af.x, af.y), a23 = pk(af.z, af.w);

            fma2(accE[0][0], a01, w0); fma2(accE[0][1], a23, w1);
            fma2(accE[1][0], a01, w1); fma2(accE[1][1], a23, w2);
            fma2(accE[2][0], a01, w2); fma2(accE[2][1], a23, w3);
            fma2(accE[3][0], a01, w3); fma2(accE[3][1], a23, w4);
            fma2(accE[4][0], a01, w4); fma2(accE[4][1], a23, w5);

            fma2(accO[0][0], a01, o0); fma2(accO[0][1], a23, o1);
            fma2(accO[1][0], a01, o1); fma2(accO[1][1], a23, o2);
            fma2(accO[2][0], a01, o2); fma2(accO[2][1], a23, o3);
            fma2(accO[3][0], a01, o3); fma2(accO[3][1], a23, o4);
        }
        if (k + 2 < NCH) {
            __syncthreads();
            stage((k + 2) * CHUNK, k & 1);
        }
    }

    // ---- unpack to per-dx floats
    float r[PATCH][4];
#pragma unroll
    for (int e = 0; e < 5; ++e) {
        unpk(accE[e][0], r[2 * e][0], r[2 * e][1]);
        unpk(accE[e][1], r[2 * e][2], r[2 * e][3]);
    }
#pragma unroll
    for (int o = 0; o < 4; ++o) {
        unpk(accO[o][0], r[2 * o + 1][0], r[2 * o + 1][1]);
        unpk(accO[o][1], r[2 * o + 1][2], r[2 * o + 1][3]);
    }

    // ---- combine channel quarters via smem (reuse staging buffers)
    __syncthreads();
    const int pid = dy * 8 + xq;               // 0..71
    float* scr = smem;                          // [3][72][CSTRIDE]
    if (ch) {
        float* slot = scr + ((ch - 1) * 72 + pid) * CSTRIDE;
#pragma unroll
        for (int d = 0; d < PATCH; ++d)
            *(float4*)(slot + d * 4) = make_float4(r[d][0], r[d][1], r[d][2], r[d][3]);
    }
    __syncthreads();
    if (ch == 0) {
#pragma unroll
        for (int g = 0; g < 3; ++g) {
            const float* slot = scr + (g * 72 + pid) * CSTRIDE;
#pragma unroll
            for (int d = 0; d < PATCH; ++d) {
                float4 p = *(const float4*)(slot + d * 4);
                r[d][0] += p.x; r[d][1] += p.y; r[d][2] += p.z; r[d][3] += p.w;
            }
        }
        float* op = out + (size_t)(b * 81 + dy * PATCH) * HW + y * Ww + xg;
#pragma unroll
        for (int d = 0; d < PATCH; ++d) {
            float4 o;
            o.x = fmaxf(r[d][0], 0.f);
            o.y = fmaxf(r[d][1], 0.f);
            o.z = fmaxf(r[d][2], 0.f);
            o.w = fmaxf(r[d][3], 0.f);
            *(float4*)(op + d * HW) = o;
        }
    }
}

// ---------------------------------------------------------------------------
extern "C" void kernel_launch(void* const* d_in, const int* in_sizes, int n_in,
                              void* d_out, int out_size) {
    const float* f1 = (const float*)d_in[0];
    const float* f2 = (const float*)d_in[1];
    float* out = (float*)d_out;

    cudaFuncSetAttribute(corr_kernel,
                         cudaFuncAttributeMaxDynamicSharedMemorySize, SMEM_BYTES);

    invnorm_kernel<<<128, 256>>>(f1, f2);
    normpad_kernel<<<2320, 256>>>(f1, f2);
    corr_kernel<<<Bz * Hh * 2, NTHR, SMEM_BYTES>>>(out);
}